// round 1
// baseline (speedup 1.0000x reference)
#include <cuda_runtime.h>
#include <cstdint>

#define N_NODES   100000
#define N_EDGES   1600000
#define VOCAB     128
#define D         30
#define DPAD      32
#define N_CLASSES 5

// Scratch (device globals: no allocation allowed in kernel_launch)
__device__ float g_bufA[N_NODES * DPAD];   // h  (layer input / output)
__device__ float g_bufB[N_NODES * DPAD];   // hs (h * inv_deg)
__device__ float g_bufC[N_NODES * DPAD];   // agg
__device__ float g_deg[N_NODES];
__device__ float g_inv[N_NODES];

// ---------------------------------------------------------------------------
// h0[n][d] = emb[x[n]][d] for d<30, 0 for pad lanes
__global__ void k_gather(const int* __restrict__ x,
                         const float* __restrict__ emb,
                         float* __restrict__ h) {
    int i = blockIdx.x * blockDim.x + threadIdx.x;
    if (i >= N_NODES * DPAD) return;
    int n = i >> 5, d = i & 31;
    float v = 0.0f;
    if (d < D) v = emb[x[n] * D + d];
    h[i] = v;
}

// deg[n] = 1 (self loop)
__global__ void k_deg_init(float* __restrict__ deg) {
    int n = blockIdx.x * blockDim.x + threadIdx.x;
    if (n < N_NODES) deg[n] = 1.0f;
}

// deg[row[e]] += 1
__global__ void k_deg_count(const int* __restrict__ row, float* __restrict__ deg) {
    int e = blockIdx.x * blockDim.x + threadIdx.x;
    if (e < N_EDGES) atomicAdd(&deg[row[e]], 1.0f);
}

__global__ void k_deg_inv(const float* __restrict__ deg, float* __restrict__ inv) {
    int n = blockIdx.x * blockDim.x + threadIdx.x;
    if (n < N_NODES) inv[n] = 1.0f / deg[n];
}

// hs = h * inv_deg ; agg initialized with self-loop contribution (= hs)
__global__ void k_scale(const float* __restrict__ h,
                        const float* __restrict__ inv,
                        float* __restrict__ hs,
                        float* __restrict__ agg) {
    int i = blockIdx.x * blockDim.x + threadIdx.x;
    if (i >= N_NODES * DPAD) return;
    float v = h[i] * inv[i >> 5];
    hs[i]  = v;
    agg[i] = v;
}

// Edge scatter: 8 threads per edge, one float4 chunk each.
// agg[col[e]][c..c+3] += hs[row[e]][c..c+3]  via vector reduction (no return).
__global__ void k_edge(const int* __restrict__ row,
                       const int* __restrict__ col,
                       const float* __restrict__ hs,
                       float* __restrict__ agg) {
    int t = blockIdx.x * blockDim.x + threadIdx.x;
    if (t >= N_EDGES * 8) return;
    int e = t >> 3;
    int c = (t & 7) << 2;             // 0,4,...,28 (chunk 7 covers pad cols 30,31 = +0)
    int r  = row[e];
    int cl = col[e];
    float4 v = *reinterpret_cast<const float4*>(hs + ((long)r << 5) + c);
    float* dst = agg + ((long)cl << 5) + c;
    asm volatile("red.global.add.v4.f32 [%0], {%1, %2, %3, %4};"
                 :: "l"(dst), "f"(v.x), "f"(v.y), "f"(v.z), "f"(v.w)
                 : "memory");
}

// hout[n][j] = relu( sum_k agg[n][k] * W[j][k] + b[j] ), one warp per node.
__global__ void k_layer_mm(const float* __restrict__ agg,
                           const float* __restrict__ W,
                           const float* __restrict__ b,
                           float* __restrict__ hout) {
    __shared__ float Wt[D * DPAD];   // Wt[k*32 + j] = W[j][k]
    int tid = threadIdx.x;
    for (int i = tid; i < D * DPAD; i += blockDim.x) {
        int k = i >> 5, j = i & 31;
        Wt[i] = (j < D) ? W[j * D + k] : 0.0f;
    }
    __syncthreads();
    int n = blockIdx.x * 8 + (tid >> 5);
    int lane = tid & 31;
    if (n >= N_NODES) return;
    const float* a = agg + ((long)n << 5);
    float acc = (lane < D) ? b[lane] : 0.0f;
    #pragma unroll
    for (int k = 0; k < D; k++)
        acc = fmaf(__ldg(a + k), Wt[(k << 5) + lane], acc);
    acc = fmaxf(acc, 0.0f);
    hout[((long)n << 5) + lane] = (lane < D) ? acc : 0.0f;
}

// out[n][j] = sum_k h[n][k] * Wout[j][k] + bout[j], one thread per node.
__global__ void k_out(const float* __restrict__ h,
                      const float* __restrict__ Wout,
                      const float* __restrict__ bout,
                      float* __restrict__ out) {
    __shared__ float Ws[N_CLASSES * D];
    __shared__ float bs[N_CLASSES];
    int tid = threadIdx.x;
    if (tid < N_CLASSES * D) Ws[tid] = Wout[tid];
    if (tid < N_CLASSES)     bs[tid] = bout[tid];
    __syncthreads();
    int n = blockIdx.x * blockDim.x + tid;
    if (n >= N_NODES) return;
    float hv[DPAD];
    const float4* hp = reinterpret_cast<const float4*>(h + ((long)n << 5));
    #pragma unroll
    for (int q = 0; q < 8; q++) {
        float4 f = hp[q];
        hv[4*q] = f.x; hv[4*q+1] = f.y; hv[4*q+2] = f.z; hv[4*q+3] = f.w;
    }
    #pragma unroll
    for (int j = 0; j < N_CLASSES; j++) {
        float acc = bs[j];
        #pragma unroll
        for (int k = 0; k < D; k++)
            acc = fmaf(hv[k], Ws[j * D + k], acc);
        out[n * N_CLASSES + j] = acc;
    }
}

// ---------------------------------------------------------------------------
extern "C" void kernel_launch(void* const* d_in, const int* in_sizes, int n_in,
                              void* d_out, int out_size) {
    const int*   x    = (const int*)  d_in[0];
    const int*   ei   = (const int*)  d_in[1];   // [2, E] row-major
    const float* emb  = (const float*)d_in[2];
    const float* W1   = (const float*)d_in[3];
    const float* b1   = (const float*)d_in[4];
    const float* W2   = (const float*)d_in[5];
    const float* b2   = (const float*)d_in[6];
    const float* W3   = (const float*)d_in[7];
    const float* b3   = (const float*)d_in[8];
    const float* Wout = (const float*)d_in[9];
    const float* bout = (const float*)d_in[10];
    float* out = (float*)d_out;

    const int* row = ei;             // edge_index[0]
    const int* col = ei + N_EDGES;   // edge_index[1]

    float *bufA, *bufB, *bufC, *deg, *inv;
    cudaGetSymbolAddress((void**)&bufA, g_bufA);
    cudaGetSymbolAddress((void**)&bufB, g_bufB);
    cudaGetSymbolAddress((void**)&bufC, g_bufC);
    cudaGetSymbolAddress((void**)&deg,  g_deg);
    cudaGetSymbolAddress((void**)&inv,  g_inv);

    const int NT = 256;
    const int gridNodeVec = (N_NODES * DPAD + NT - 1) / NT;   // 12500
    const int gridNode    = (N_NODES + NT - 1) / NT;
    const int gridEdge    = (N_EDGES + NT - 1) / NT;
    const int gridEdge8   = (N_EDGES * 8 + NT - 1) / NT;      // 50000
    const int gridMM      = (N_NODES + 7) / 8;                // 12500

    // h0 = emb[x]
    k_gather<<<gridNodeVec, NT>>>(x, emb, bufA);

    // degree (once; reused by all layers)
    k_deg_init<<<gridNode, NT>>>(deg);
    k_deg_count<<<gridEdge, NT>>>(row, deg);
    k_deg_inv<<<gridNode, NT>>>(deg, inv);

    const float* Ws[3] = {W1, W2, W3};
    const float* bs[3] = {b1, b2, b3};
    for (int l = 0; l < 3; l++) {
        k_scale<<<gridNodeVec, NT>>>(bufA, inv, bufB, bufC);   // hs + self-loop init
        k_edge<<<gridEdge8, NT>>>(row, col, bufB, bufC);       // scatter-add
        k_layer_mm<<<gridMM, NT>>>(bufC, Ws[l], bs[l], bufA);  // relu(agg @ W^T + b)
    }

    k_out<<<gridNode, NT>>>(bufA, Wout, bout, out);
}

// round 2
// speedup vs baseline: 1.4247x; 1.4247x over previous
#include <cuda_runtime.h>
#include <cstdint>

#define N_NODES   100000
#define N_EDGES   1600000
#define VOCAB     128
#define D         30
#define DPAD      32
#define N_CLASSES 5
#define NB_SCAN   392        // 392 * 256 = 100352 >= N_NODES

// Scratch (device globals: no allocation allowed)
__device__ float g_hsA[N_NODES * DPAD];
__device__ float g_hsB[N_NODES * DPAD];
__device__ float g_h  [N_NODES * DPAD];
__device__ float g_inv[N_NODES];
__device__ int   g_cnt [N_NODES];      // in-degree (by col)
__device__ int   g_degr[N_NODES];      // out-degree (by row) for normalization
__device__ int   g_off [N_NODES + 1];  // CSR offsets by destination
__device__ int   g_cur [N_NODES];      // scatter cursors
__device__ int   g_part[NB_SCAN];      // scan partials
__device__ int   g_srow[N_EDGES];      // CSR payload: source node per in-edge

// ---------------------------------------------------------------------------
__global__ void k_zero(int* __restrict__ cnt, int* __restrict__ degr) {
    int n = blockIdx.x * blockDim.x + threadIdx.x;
    if (n < N_NODES) { cnt[n] = 0; degr[n] = 0; }
}

__global__ void k_hist(const int* __restrict__ row, const int* __restrict__ col,
                       int* __restrict__ cnt, int* __restrict__ degr) {
    int e = blockIdx.x * blockDim.x + threadIdx.x;
    if (e < N_EDGES) {
        atomicAdd(&cnt[col[e]], 1);
        atomicAdd(&degr[row[e]], 1);
    }
}

__global__ void k_inv(const int* __restrict__ degr, float* __restrict__ inv) {
    int n = blockIdx.x * blockDim.x + threadIdx.x;
    if (n < N_NODES) inv[n] = 1.0f / (1.0f + (float)degr[n]);  // +1 = self loop
}

// ---- 3-phase exclusive scan over cnt -> off (and cursor init) ----
__global__ void k_scanA(const int* __restrict__ cnt, int* __restrict__ part) {
    __shared__ int s[256];
    int i = blockIdx.x * 256 + threadIdx.x;
    s[threadIdx.x] = (i < N_NODES) ? cnt[i] : 0;
    __syncthreads();
    for (int st = 128; st > 0; st >>= 1) {
        if (threadIdx.x < st) s[threadIdx.x] += s[threadIdx.x + st];
        __syncthreads();
    }
    if (threadIdx.x == 0) part[blockIdx.x] = s[0];
}

__global__ void k_scanB(int* __restrict__ part) {
    __shared__ int s[512];
    int t = threadIdx.x;
    s[t] = (t < NB_SCAN) ? part[t] : 0;
    __syncthreads();
    for (int st = 1; st < 512; st <<= 1) {
        int u = (t >= st) ? s[t - st] : 0;
        __syncthreads();
        s[t] += u;
        __syncthreads();
    }
    if (t < NB_SCAN) part[t] = (t == 0) ? 0 : s[t - 1];   // exclusive
}

__global__ void k_scanC(const int* __restrict__ cnt, const int* __restrict__ part,
                        int* __restrict__ off, int* __restrict__ cur) {
    __shared__ int s[256];
    int i = blockIdx.x * 256 + threadIdx.x;
    int v = (i < N_NODES) ? cnt[i] : 0;
    s[threadIdx.x] = v;
    __syncthreads();
    for (int st = 1; st < 256; st <<= 1) {
        int u = (threadIdx.x >= st) ? s[threadIdx.x - st] : 0;
        __syncthreads();
        s[threadIdx.x] += u;
        __syncthreads();
    }
    int excl = part[blockIdx.x] + s[threadIdx.x] - v;
    if (i < N_NODES) { off[i] = excl; cur[i] = excl; }
    if (i == N_NODES - 1) off[N_NODES] = excl + v;
}

__global__ void k_scatter(const int* __restrict__ row, const int* __restrict__ col,
                          int* __restrict__ cur, int* __restrict__ srow) {
    int e = blockIdx.x * blockDim.x + threadIdx.x;
    if (e < N_EDGES) {
        int p = atomicAdd(&cur[col[e]], 1);
        srow[p] = row[e];
    }
}

// ---------------------------------------------------------------------------
// hs0[n][d] = emb[x[n]][d] * inv[n]  (pad lanes zero)
__global__ void k_gather(const int* __restrict__ x, const float* __restrict__ emb,
                         const float* __restrict__ inv, float* __restrict__ hs) {
    int i = blockIdx.x * blockDim.x + threadIdx.x;
    if (i >= N_NODES * DPAD) return;
    int n = i >> 5, d = i & 31;
    float v = (d < D) ? emb[x[n] * D + d] * inv[n] : 0.0f;
    hs[i] = v;
}

// Fused layer: warp per node.
//   agg[lane] = hs[n][lane] + sum_{in-edges} hs[src][lane]   (register, no atomics)
//   h_out[n][j]  = relu(sum_k agg[k] * W[j][k] + b[j])
//   hs_out[n][j] = h_out[n][j] * inv[n]
__global__ void __launch_bounds__(256)
k_layer(const int* __restrict__ off, const int* __restrict__ srow,
        const float* __restrict__ hs,
        const float* __restrict__ W, const float* __restrict__ b,
        const float* __restrict__ inv,
        float* __restrict__ h_out, float* __restrict__ hs_out) {
    __shared__ float Wt[D * DPAD];       // Wt[k*32 + j] = W[j][k]
    __shared__ float bsm[DPAD];
    __shared__ float sAgg[8][DPAD];
    int tid = threadIdx.x;
    for (int i = tid; i < D * DPAD; i += 256) {
        int k = i >> 5, j = i & 31;
        Wt[i] = (j < D) ? W[j * D + k] : 0.0f;
    }
    if (tid < DPAD) bsm[tid] = (tid < D) ? b[tid] : 0.0f;
    __syncthreads();

    int w = tid >> 5, lane = tid & 31;
    int n = blockIdx.x * 8 + w;
    if (n >= N_NODES) return;

    int beg = off[n], end = off[n + 1];
    float acc0 = hs[(n << 5) + lane];    // self loop
    float acc1 = 0.0f;
    int i2 = beg;
    for (; i2 + 1 < end; i2 += 2) {
        int s0 = __ldg(&srow[i2]);
        int s1 = __ldg(&srow[i2 + 1]);
        acc0 += hs[(s0 << 5) + lane];
        acc1 += hs[(s1 << 5) + lane];
    }
    if (i2 < end) acc0 += hs[(__ldg(&srow[i2]) << 5) + lane];
    sAgg[w][lane] = acc0 + acc1;
    __syncwarp();

    float o = bsm[lane];
    #pragma unroll
    for (int k = 0; k < D; k++)
        o = fmaf(sAgg[w][k], Wt[(k << 5) + lane], o);
    o = fmaxf(o, 0.0f);
    float oh = (lane < D) ? o : 0.0f;
    h_out [(n << 5) + lane] = oh;
    hs_out[(n << 5) + lane] = oh * inv[n];
}

// out[n][j] = sum_k h[n][k] * Wout[j][k] + bout[j], one thread per node.
__global__ void k_out(const float* __restrict__ h, const float* __restrict__ Wout,
                      const float* __restrict__ bout, float* __restrict__ out) {
    __shared__ float Ws[N_CLASSES * D];
    __shared__ float bs[N_CLASSES];
    int tid = threadIdx.x;
    if (tid < N_CLASSES * D) Ws[tid] = Wout[tid];
    if (tid < N_CLASSES)     bs[tid] = bout[tid];
    __syncthreads();
    int n = blockIdx.x * blockDim.x + tid;
    if (n >= N_NODES) return;
    float hv[DPAD];
    const float4* hp = reinterpret_cast<const float4*>(h + ((long)n << 5));
    #pragma unroll
    for (int q = 0; q < 8; q++) {
        float4 f = hp[q];
        hv[4*q] = f.x; hv[4*q+1] = f.y; hv[4*q+2] = f.z; hv[4*q+3] = f.w;
    }
    #pragma unroll
    for (int j = 0; j < N_CLASSES; j++) {
        float acc = bs[j];
        #pragma unroll
        for (int k = 0; k < D; k++)
            acc = fmaf(hv[k], Ws[j * D + k], acc);
        out[n * N_CLASSES + j] = acc;
    }
}

// ---------------------------------------------------------------------------
extern "C" void kernel_launch(void* const* d_in, const int* in_sizes, int n_in,
                              void* d_out, int out_size) {
    const int*   x    = (const int*)  d_in[0];
    const int*   ei   = (const int*)  d_in[1];   // [2, E] row-major
    const float* emb  = (const float*)d_in[2];
    const float* W1   = (const float*)d_in[3];
    const float* b1   = (const float*)d_in[4];
    const float* W2   = (const float*)d_in[5];
    const float* b2   = (const float*)d_in[6];
    const float* W3   = (const float*)d_in[7];
    const float* b3   = (const float*)d_in[8];
    const float* Wout = (const float*)d_in[9];
    const float* bout = (const float*)d_in[10];
    float* out = (float*)d_out;

    const int* row = ei;
    const int* col = ei + N_EDGES;

    float *hsA, *hsB, *hbuf, *inv;
    int *cnt, *degr, *off, *cur, *part, *srow;
    cudaGetSymbolAddress((void**)&hsA,  g_hsA);
    cudaGetSymbolAddress((void**)&hsB,  g_hsB);
    cudaGetSymbolAddress((void**)&hbuf, g_h);
    cudaGetSymbolAddress((void**)&inv,  g_inv);
    cudaGetSymbolAddress((void**)&cnt,  g_cnt);
    cudaGetSymbolAddress((void**)&degr, g_degr);
    cudaGetSymbolAddress((void**)&off,  g_off);
    cudaGetSymbolAddress((void**)&cur,  g_cur);
    cudaGetSymbolAddress((void**)&part, g_part);
    cudaGetSymbolAddress((void**)&srow, g_srow);

    const int NT = 256;
    const int gNode    = (N_NODES + NT - 1) / NT;
    const int gNodeVec = (N_NODES * DPAD + NT - 1) / NT;
    const int gEdge    = (N_EDGES + NT - 1) / NT;
    const int gMM      = (N_NODES + 7) / 8;

    // --- one-time graph preprocessing (reused by all 3 layers) ---
    k_zero   <<<gNode, NT>>>(cnt, degr);
    k_hist   <<<gEdge, NT>>>(row, col, cnt, degr);
    k_inv    <<<gNode, NT>>>(degr, inv);
    k_scanA  <<<NB_SCAN, 256>>>(cnt, part);
    k_scanB  <<<1, 512>>>(part);
    k_scanC  <<<NB_SCAN, 256>>>(cnt, part, off, cur);
    k_scatter<<<gEdge, NT>>>(row, col, cur, srow);

    // --- h0 (pre-scaled by inv_deg) ---
    k_gather<<<gNodeVec, NT>>>(x, emb, inv, hsA);

    // --- three fused layers, no atomics ---
    k_layer<<<gMM, NT>>>(off, srow, hsA, W1, b1, inv, hbuf, hsB);
    k_layer<<<gMM, NT>>>(off, srow, hsB, W2, b2, inv, hbuf, hsA);
    k_layer<<<gMM, NT>>>(off, srow, hsA, W3, b3, inv, hbuf, hsB);

    k_out<<<gNode, NT>>>(hbuf, Wout, bout, out);
}

// round 3
// speedup vs baseline: 1.7504x; 1.2286x over previous
#include <cuda_runtime.h>
#include <cuda_fp16.h>
#include <cstdint>

#define N_NODES   100000
#define N_EDGES   1600000
#define VOCAB     128
#define D         30
#define DPAD      32
#define HPAD      16         // half2 per node row (32 features as 16 half2 = 64B)
#define N_CLASSES 5
#define NB_SCAN   392        // 392 * 256 = 100352 >= N_NODES

// Scratch (device globals: no allocation allowed)
__device__ __half2 g_hsA[N_NODES * HPAD];
__device__ __half2 g_hsB[N_NODES * HPAD];
__device__ float   g_inv[N_NODES];
__device__ int     g_cnt [N_NODES];      // in-degree (by col)
__device__ int     g_degr[N_NODES];      // out-degree (by row)
__device__ int     g_off [N_NODES + 1];  // CSR offsets by destination
__device__ int     g_cur [N_NODES];      // scatter cursors
__device__ int     g_part[NB_SCAN];      // scan partials
__device__ int     g_srow[N_EDGES];      // CSR payload: source node per in-edge

// ---------------------------------------------------------------------------
__global__ void k_zero(int* __restrict__ cnt, int* __restrict__ degr) {
    int n = blockIdx.x * blockDim.x + threadIdx.x;
    if (n < N_NODES) { cnt[n] = 0; degr[n] = 0; }
}

__global__ void k_hist(const int* __restrict__ row, const int* __restrict__ col,
                       int* __restrict__ cnt, int* __restrict__ degr) {
    int e = blockIdx.x * blockDim.x + threadIdx.x;
    if (e < N_EDGES) {
        atomicAdd(&cnt[col[e]], 1);
        atomicAdd(&degr[row[e]], 1);
    }
}

// ---- 3-phase exclusive scan over cnt -> off (+ cursor + inv_deg init) ----
__global__ void k_scanA(const int* __restrict__ cnt, int* __restrict__ part) {
    __shared__ int s[256];
    int i = blockIdx.x * 256 + threadIdx.x;
    s[threadIdx.x] = (i < N_NODES) ? cnt[i] : 0;
    __syncthreads();
    for (int st = 128; st > 0; st >>= 1) {
        if (threadIdx.x < st) s[threadIdx.x] += s[threadIdx.x + st];
        __syncthreads();
    }
    if (threadIdx.x == 0) part[blockIdx.x] = s[0];
}

__global__ void k_scanB(int* __restrict__ part) {
    __shared__ int s[512];
    int t = threadIdx.x;
    s[t] = (t < NB_SCAN) ? part[t] : 0;
    __syncthreads();
    for (int st = 1; st < 512; st <<= 1) {
        int u = (t >= st) ? s[t - st] : 0;
        __syncthreads();
        s[t] += u;
        __syncthreads();
    }
    if (t < NB_SCAN) part[t] = (t == 0) ? 0 : s[t - 1];   // exclusive
}

__global__ void k_scanC(const int* __restrict__ cnt, const int* __restrict__ part,
                        const int* __restrict__ degr,
                        int* __restrict__ off, int* __restrict__ cur,
                        float* __restrict__ inv) {
    __shared__ int s[256];
    int i = blockIdx.x * 256 + threadIdx.x;
    int v = (i < N_NODES) ? cnt[i] : 0;
    s[threadIdx.x] = v;
    __syncthreads();
    for (int st = 1; st < 256; st <<= 1) {
        int u = (threadIdx.x >= st) ? s[threadIdx.x - st] : 0;
        __syncthreads();
        s[threadIdx.x] += u;
        __syncthreads();
    }
    int excl = part[blockIdx.x] + s[threadIdx.x] - v;
    if (i < N_NODES) {
        off[i] = excl;
        cur[i] = excl;
        inv[i] = 1.0f / (1.0f + (float)degr[i]);   // +1 = self loop
    }
    if (i == N_NODES - 1) off[N_NODES] = excl + v;
}

__global__ void k_scatter(const int* __restrict__ row, const int* __restrict__ col,
                          int* __restrict__ cur, int* __restrict__ srow) {
    int e = blockIdx.x * blockDim.x + threadIdx.x;
    if (e < N_EDGES) {
        int p = atomicAdd(&cur[col[e]], 1);
        srow[p] = row[e];
    }
}

// ---------------------------------------------------------------------------
// hs0[n] = half2-packed emb[x[n]] * inv[n]
__global__ void k_gather(const int* __restrict__ x, const float* __restrict__ emb,
                         const float* __restrict__ inv, __half2* __restrict__ hs) {
    int i = blockIdx.x * blockDim.x + threadIdx.x;
    if (i >= N_NODES * HPAD) return;
    int n = i >> 4, l = i & 15;
    float iv = inv[n];
    int xv = x[n];
    float v0 = (2 * l     < D) ? emb[xv * D + 2 * l]     * iv : 0.0f;
    float v1 = (2 * l + 1 < D) ? emb[xv * D + 2 * l + 1] * iv : 0.0f;
    hs[i] = __floats2half2_rn(v0, v1);
}

// Fused layer: 16-lane group per node (16 nodes / 256-thread block, grid=6250 exact).
//   agg = hs[n] + sum_{in-edges} hs[src]   (fp32 accum, fp16 loads, no atomics)
//   o[j] = relu(sum_k agg[k]*W[j][k] + b[j])
//   FINAL=false: hs_out[n] = fp16(o * inv[n])
//   FINAL=true : out[n][j] = sum_k o[k]*Wout[j][k] + bout[j]
template <bool FINAL>
__global__ void __launch_bounds__(256)
k_layer(const int* __restrict__ off, const int* __restrict__ srow,
        const __half2* __restrict__ hs,
        const float* __restrict__ W, const float* __restrict__ b,
        const float* __restrict__ inv,
        __half2* __restrict__ hs_out,
        const float* __restrict__ Wout, const float* __restrict__ bout,
        float* __restrict__ out) {
    __shared__ float2 Wt2[D * 16];     // Wt2[k*16+l] = (W[2l][k], W[2l+1][k])
    __shared__ float2 b2s[16];
    __shared__ float  sAgg[16][DPAD];
    __shared__ float  Wo[N_CLASSES * D];
    __shared__ float  bo[N_CLASSES];

    int tid = threadIdx.x;
    for (int i = tid; i < D * 16; i += 256) {
        int l = i & 15, k = i >> 4;
        float w0 = (2 * l     < D) ? W[(2 * l)     * D + k] : 0.0f;
        float w1 = (2 * l + 1 < D) ? W[(2 * l + 1) * D + k] : 0.0f;
        Wt2[i] = make_float2(w0, w1);
    }
    if (tid < 16) {
        int l = tid;
        b2s[l] = make_float2((2 * l < D) ? b[2 * l] : 0.0f,
                             (2 * l + 1 < D) ? b[2 * l + 1] : 0.0f);
    }
    if (FINAL) {
        if (tid < N_CLASSES * D) Wo[tid] = Wout[tid];
        if (tid < N_CLASSES)     bo[tid] = bout[tid];
    }
    __syncthreads();

    int g = tid >> 4, l = tid & 15;
    int n = blockIdx.x * 16 + g;            // grid covers exactly N_NODES

    int beg = off[n], end = off[n + 1];
    float2 a0 = __half22float2(hs[(n << 4) + l]);   // self loop
    float2 a1 = make_float2(0.f, 0.f);
    float2 a2 = make_float2(0.f, 0.f);
    float2 a3 = make_float2(0.f, 0.f);
    int i = beg;
    for (; i + 3 < end; i += 4) {
        int s0 = __ldg(srow + i);
        int s1 = __ldg(srow + i + 1);
        int s2 = __ldg(srow + i + 2);
        int s3 = __ldg(srow + i + 3);
        float2 v0 = __half22float2(hs[(s0 << 4) + l]);
        float2 v1 = __half22float2(hs[(s1 << 4) + l]);
        float2 v2 = __half22float2(hs[(s2 << 4) + l]);
        float2 v3 = __half22float2(hs[(s3 << 4) + l]);
        a0.x += v0.x; a0.y += v0.y;
        a1.x += v1.x; a1.y += v1.y;
        a2.x += v2.x; a2.y += v2.y;
        a3.x += v3.x; a3.y += v3.y;
    }
    for (; i < end; i++) {
        float2 v = __half22float2(hs[(__ldg(srow + i) << 4) + l]);
        a0.x += v.x; a0.y += v.y;
    }
    sAgg[g][2 * l]     = a0.x + a1.x + a2.x + a3.x;
    sAgg[g][2 * l + 1] = a0.y + a1.y + a2.y + a3.y;
    __syncwarp();

    float2 o = b2s[l];
    #pragma unroll
    for (int k = 0; k < D; k++) {
        float av = sAgg[g][k];
        float2 w = Wt2[(k << 4) + l];
        o.x = fmaf(av, w.x, o.x);
        o.y = fmaf(av, w.y, o.y);
    }
    o.x = fmaxf(o.x, 0.0f);
    o.y = fmaxf(o.y, 0.0f);
    if (2 * l >= D)     o.x = 0.0f;   // pad lanes (l == 15)
    if (2 * l + 1 >= D) o.y = 0.0f;

    if (!FINAL) {
        float iv = inv[n];
        hs_out[(n << 4) + l] = __floats2half2_rn(o.x * iv, o.y * iv);
    } else {
        __syncwarp();                  // everyone done reading sAgg
        sAgg[g][2 * l]     = o.x;
        sAgg[g][2 * l + 1] = o.y;
        __syncwarp();
        if (l < N_CLASSES) {
            float acc = bo[l];
            #pragma unroll
            for (int k = 0; k < D; k++)
                acc = fmaf(sAgg[g][k], Wo[l * D + k], acc);
            out[n * N_CLASSES + l] = acc;
        }
    }
}

// ---------------------------------------------------------------------------
extern "C" void kernel_launch(void* const* d_in, const int* in_sizes, int n_in,
                              void* d_out, int out_size) {
    const int*   x    = (const int*)  d_in[0];
    const int*   ei   = (const int*)  d_in[1];   // [2, E] row-major
    const float* emb  = (const float*)d_in[2];
    const float* W1   = (const float*)d_in[3];
    const float* b1   = (const float*)d_in[4];
    const float* W2   = (const float*)d_in[5];
    const float* b2   = (const float*)d_in[6];
    const float* W3   = (const float*)d_in[7];
    const float* b3   = (const float*)d_in[8];
    const float* Wout = (const float*)d_in[9];
    const float* bout = (const float*)d_in[10];
    float* out = (float*)d_out;

    const int* row = ei;
    const int* col = ei + N_EDGES;

    __half2 *hsA, *hsB;
    float *inv;
    int *cnt, *degr, *off, *cur, *part, *srow;
    cudaGetSymbolAddress((void**)&hsA,  g_hsA);
    cudaGetSymbolAddress((void**)&hsB,  g_hsB);
    cudaGetSymbolAddress((void**)&inv,  g_inv);
    cudaGetSymbolAddress((void**)&cnt,  g_cnt);
    cudaGetSymbolAddress((void**)&degr, g_degr);
    cudaGetSymbolAddress((void**)&off,  g_off);
    cudaGetSymbolAddress((void**)&cur,  g_cur);
    cudaGetSymbolAddress((void**)&part, g_part);
    cudaGetSymbolAddress((void**)&srow, g_srow);

    const int NT = 256;
    const int gNode   = (N_NODES + NT - 1) / NT;
    const int gNodeH  = (N_NODES * HPAD + NT - 1) / NT;
    const int gEdge   = (N_EDGES + NT - 1) / NT;
    const int gLayer  = N_NODES / 16;   // 6250, exact

    // --- one-time graph preprocessing (reused by all 3 layers) ---
    k_zero   <<<gNode, NT>>>(cnt, degr);
    k_hist   <<<gEdge, NT>>>(row, col, cnt, degr);
    k_scanA  <<<NB_SCAN, 256>>>(cnt, part);
    k_scanB  <<<1, 512>>>(part);
    k_scanC  <<<NB_SCAN, 256>>>(cnt, part, degr, off, cur, inv);
    k_scatter<<<gEdge, NT>>>(row, col, cur, srow);

    // --- h0 (pre-scaled by inv_deg, fp16) ---
    k_gather<<<gNodeH, NT>>>(x, emb, inv, hsA);

    // --- three fused layers, no atomics; final layer emits logits ---
    k_layer<false><<<gLayer, NT>>>(off, srow, hsA, W1, b1, inv, hsB,
                                   nullptr, nullptr, nullptr);
    k_layer<false><<<gLayer, NT>>>(off, srow, hsB, W2, b2, inv, hsA,
                                   nullptr, nullptr, nullptr);
    k_layer<true> <<<gLayer, NT>>>(off, srow, hsA, W3, b3, inv, nullptr,
                                   Wout, bout, out);
}